// round 7
// baseline (speedup 1.0000x reference)
#include <cuda_runtime.h>
#include <cuda_bf16.h>
#include <cstdint>

#define STARTP 4080

// ---------------------------------------------------------------------------
// Device-global scratch (no allocations allowed)
// ---------------------------------------------------------------------------
__device__ float g_qkv[256 * 6144];                              // fp32 q|k|v (post-RoPE)
__device__ __nv_bfloat16 g_x_h [256*4096], g_x_l [256*4096];     // x planes
__device__ __nv_bfloat16 g_at_h[256*4096], g_at_l[256*4096];     // attn planes
__device__ float g_po[2 * 256 * 4096];                           // split-KV partial O
__device__ float g_ml[2 * 256 * 32 * 2];                         // split-KV (m, l)

// ---------------------------------------------------------------------------
// helpers
// ---------------------------------------------------------------------------
__device__ __forceinline__ uint32_t packbf(float a, float b) {  // a->lo16, b->hi16
    uint32_t u;
    asm("cvt.rn.bf16x2.f32 %0, %1, %2;" : "=r"(u) : "f"(b), "f"(a));
    return u;
}
__device__ __forceinline__ void split2(float a, float b, uint32_t& h, uint32_t& l) {
    h = packbf(a, b);
    float ra = a - __uint_as_float(h << 16);
    float rb = b - __uint_as_float(h & 0xffff0000u);
    l = packbf(ra, rb);
}

__device__ __forceinline__ void mma16(float* c, const uint32_t* a,
                                      uint32_t b0, uint32_t b1) {
    asm("mma.sync.aligned.m16n8k16.row.col.f32.bf16.bf16.f32 "
        "{%0,%1,%2,%3}, {%4,%5,%6,%7}, {%8,%9}, {%0,%1,%2,%3};"
        : "+f"(c[0]), "+f"(c[1]), "+f"(c[2]), "+f"(c[3])
        : "r"(a[0]), "r"(a[1]), "r"(a[2]), "r"(a[3]), "r"(b0), "r"(b1));
}

__device__ __forceinline__ void ldsm4(uint32_t* r, uint32_t addr) {
    asm volatile("ldmatrix.sync.aligned.m8n8.x4.shared.b16 {%0,%1,%2,%3}, [%4];"
        : "=r"(r[0]), "=r"(r[1]), "=r"(r[2]), "=r"(r[3]) : "r"(addr));
}
__device__ __forceinline__ void ldsm4t(uint32_t* r, uint32_t addr) {
    asm volatile("ldmatrix.sync.aligned.m8n8.x4.trans.shared.b16 {%0,%1,%2,%3}, [%4];"
        : "=r"(r[0]), "=r"(r[1]), "=r"(r[2]), "=r"(r[3]) : "r"(addr));
}

// ---------------------------------------------------------------------------
// fp32 -> bf16 hi/lo planes (only for x: 4 MB)
// ---------------------------------------------------------------------------
__global__ __launch_bounds__(256) void convert_kernel(
    const float* __restrict__ in, __nv_bfloat16* __restrict__ oh,
    __nv_bfloat16* __restrict__ ol, int n4)
{
    int i = blockIdx.x * 256 + threadIdx.x;
    if (i >= n4) return;
    float4 v = ((const float4*)in)[i];
    uint32_t h0, l0, h1, l1;
    split2(v.x, v.y, h0, l0);
    split2(v.z, v.w, h1, l1);
    ((uint2*)oh)[i] = make_uint2(h0, h1);
    ((uint2*)ol)[i] = make_uint2(l0, l1);
}

// ---------------------------------------------------------------------------
// bf16x3 GEMM: C[M,N] = A[M,4096] @ B[4096,N] + bias (fp32 out).
// Block 64M x 64N, BK=32, 256 thr = 8 warps (4m x 2n => 2 warps/SMSP).
// A: pre-split bf16 planes. B: fp32, register-prefetched + split in-loop.
// Optional fused RoPE epilogue (QKV projection: global cols < 5120).
// ---------------------------------------------------------------------------
template<bool ROPE>
__global__ __launch_bounds__(256) void gemm_bf16x3(
    const __nv_bfloat16* __restrict__ Ah, const __nv_bfloat16* __restrict__ Al,
    const float* B0, int ldb0, const float* bias0, int split1,
    const float* B1, int ldb1, const float* bias1, int split2_,
    const float* B2, int ldb2, const float* bias2,
    float* __restrict__ C, int ldc,
    const float* __restrict__ cos_t, const float* __restrict__ sin_t)
{
    extern __shared__ char smraw[];
    __nv_bfloat16* As = (__nv_bfloat16*)smraw;      // [2][2][64][40]
    __nv_bfloat16* Bs = As + 2*2*64*40;             // [2][2][32][72]

    const int n0 = blockIdx.x * 64;
    const int m0 = blockIdx.y * 64;

    const float* Bp; int ldb; const float* bias; int nloc;
    if (n0 < split1)       { Bp = B0; ldb = ldb0; bias = bias0; nloc = n0; }
    else if (n0 < split2_) { Bp = B1; ldb = ldb1; bias = bias1; nloc = n0 - split1; }
    else                   { Bp = B2; ldb = ldb2; bias = bias2; nloc = n0 - split2_; }

    const int tid = threadIdx.x, lane = tid & 31, warp = tid >> 5;
    const int g = lane >> 2, tig = lane & 3;
    const int wm = warp & 3, wn = warp >> 2;
    const int lr = lane & 7, mt = lane >> 3;

    const uint32_t sA = (uint32_t)__cvta_generic_to_shared(As);
    const uint32_t sB = (uint32_t)__cvta_generic_to_shared(Bs);

    uint4  pa[2];
    float4 pb[2];

    auto fetch = [&](int ck) {
        #pragma unroll
        for (int i = 0; i < 2; ++i) {
            int idx = tid + 256 * i;                       // 0..511
            int p = idx >> 8, rem = idx & 255, row = rem >> 2, seg = rem & 3;
            pa[i] = *(const uint4*)((p ? Al : Ah)
                + (size_t)(m0 + row) * 4096 + ck * 32 + seg * 8);
        }
        #pragma unroll
        for (int i = 0; i < 2; ++i) {
            int idx = tid + 256 * i;                       // 0..511
            int row = idx >> 4, c4 = idx & 15;
            pb[i] = *(const float4*)(Bp + (size_t)(ck * 32 + row) * ldb + nloc + c4 * 4);
        }
    };

    float acc[4][4];
    #pragma unroll
    for (int nf = 0; nf < 4; ++nf)
        #pragma unroll
        for (int j = 0; j < 4; ++j) acc[nf][j] = 0.f;

    fetch(0);

    for (int ck = 0; ck < 128; ++ck) {
        const int s = ck & 1;

        #pragma unroll
        for (int i = 0; i < 2; ++i) {
            int idx = tid + 256 * i;
            int p = idx >> 8, rem = idx & 255, row = rem >> 2, seg = rem & 3;
            *(uint4*)&As[((s*2 + p)*64 + row)*40 + seg*8] = pa[i];
        }
        #pragma unroll
        for (int i = 0; i < 2; ++i) {
            int idx = tid + 256 * i;
            int row = idx >> 4, c4 = idx & 15;
            float4 v = pb[i];
            uint32_t h0, l0, h1, l1;
            split2(v.x, v.y, h0, l0);
            split2(v.z, v.w, h1, l1);
            *(uint2*)&Bs[((s*2 + 0)*32 + row)*72 + c4*4] = make_uint2(h0, h1);
            *(uint2*)&Bs[((s*2 + 1)*32 + row)*72 + c4*4] = make_uint2(l0, l1);
        }

        if (ck + 1 < 128) fetch(ck + 1);
        __syncthreads();

        #pragma unroll
        for (int ks = 0; ks < 2; ++ks) {
            int k0 = ks * 16;
            uint32_t ah[4], al[4];
            {
                int row = wm*16 + (mt & 1)*8 + lr;
                int col = k0 + (mt >> 1)*8;
                ldsm4(ah, sA + (uint32_t)((((s*2+0)*64 + row)*40 + col)*2));
                ldsm4(al, sA + (uint32_t)((((s*2+1)*64 + row)*40 + col)*2));
            }
            #pragma unroll
            for (int ng = 0; ng < 2; ++ng) {
                int brow = k0 + (mt & 1)*8 + lr;
                int bcol = wn*32 + ng*16 + (mt >> 1)*8;
                uint32_t bh[4], bl[4];
                ldsm4t(bh, sB + (uint32_t)((((s*2+0)*32 + brow)*72 + bcol)*2));
                ldsm4t(bl, sB + (uint32_t)((((s*2+1)*32 + brow)*72 + bcol)*2));
                #pragma unroll
                for (int h = 0; h < 2; ++h) {
                    int nf = ng*2 + h;
                    mma16(acc[nf], ah, bh[2*h], bh[2*h+1]);
                    mma16(acc[nf], ah, bl[2*h], bl[2*h+1]);
                    mma16(acc[nf], al, bh[2*h], bh[2*h+1]);
                }
            }
        }
    }

    __syncthreads();
    #pragma unroll
    for (int nf = 0; nf < 4; ++nf) {
        int r0 = m0 + wm*16 + g;
        int cl = wn*32 + nf*8 + 2*tig;
        int gc = n0 + cl;
        float b0v = bias[nloc + cl], b1v = bias[nloc + cl + 1];
        float c0 = acc[nf][0] + b0v, c1 = acc[nf][1] + b1v;
        float c2 = acc[nf][2] + b0v, c3 = acc[nf][3] + b1v;
        if (ROPE && gc < 5120) {
            int p = (gc & 127) >> 1;
            float cs0 = cos_t[(r0 & 15)*64 + p],       sn0 = sin_t[(r0 & 15)*64 + p];
            float cs1 = cos_t[((r0 + 8) & 15)*64 + p], sn1 = sin_t[((r0 + 8) & 15)*64 + p];
            float t0 = c0*cs0 - c1*sn0, t1 = c0*sn0 + c1*cs0;
            float t2 = c2*cs1 - c3*sn1, t3 = c2*sn1 + c3*cs1;
            c0 = t0; c1 = t1; c2 = t2; c3 = t3;
        }
        *(float2*)(C + (size_t)r0 * ldc + gc)       = make_float2(c0, c1);
        *(float2*)(C + (size_t)(r0 + 8) * ldc + gc) = make_float2(c2, c3);
    }
}

// ---------------------------------------------------------------------------
// bf16x3 flash attention, split-KV x2. Grid 256 = 2 splits x (16 b x 8 kvh).
// 256 threads: warps 0-3 consumers (head w), warps 4-7 producers.
// 32-key tiles, double-buffered bf16 hi/lo K/V planes; Q in persistent smem
// planes (keeps regs <= 128 so 2 CTAs co-reside per SM).
// Partial (O, m, l) written to globals; merge_kernel combines exactly.
// ---------------------------------------------------------------------------
__global__ __launch_bounds__(256, 2) void attn_bf16x3(
    const float* __restrict__ cache_k, const float* __restrict__ cache_v)
{
    extern __shared__ char smraw[];
    __nv_bfloat16* Qh = (__nv_bfloat16*)smraw;   // [64][136]
    __nv_bfloat16* Ql = Qh + 8704;
    __nv_bfloat16* KV = Ql + 8704;               // Kh[2][32][136] Kl Vh Vl

    const int tid = threadIdx.x, lane = tid & 31, w = tid >> 5;
    const int g = lane >> 2, tig = lane & 3;
    const int lr = lane & 7, mt = lane >> 3;
    const int blk = blockIdx.x;
    const int kvh = blk & 7, b = (blk >> 3) & 15, split = blk >> 7;
    const int kb0 = split * 2048;
    const int ptid = tid & 127;
    const float scale = 0.08838834764831843f;    // 1/sqrt(128)
    const float* qkv = g_qkv;

    // ---- stage Q: fp32 (scaled) -> bf16 hi/lo planes ----
    for (int i = tid; i < 64 * 32; i += 256) {
        int r = i >> 5, c4 = (i & 31) << 2;
        const float* src = qkv + (size_t)(b * 16 + (r & 15)) * 6144
                         + (kvh * 4 + (r >> 4)) * 128 + c4;
        float4 v = *(const float4*)src;
        v.x *= scale; v.y *= scale; v.z *= scale; v.w *= scale;
        uint32_t h0, l0, h1, l1;
        split2(v.x, v.y, h0, l0);
        split2(v.z, v.w, h1, l1);
        *(uint32_t*)&Qh[r*136 + c4]     = h0;
        *(uint32_t*)&Qh[r*136 + c4 + 2] = h1;
        *(uint32_t*)&Ql[r*136 + c4]     = l0;
        *(uint32_t*)&Ql[r*136 + c4 + 2] = l1;
    }

    const uint32_t qh_b = (uint32_t)__cvta_generic_to_shared(Qh);
    const uint32_t ql_b = (uint32_t)__cvta_generic_to_shared(Ql);
    const uint32_t kv_b = (uint32_t)__cvta_generic_to_shared(KV);
    const uint32_t kh_o = 0, kl_o = 17408, vh_o = 34816, vl_o = 52224; // bytes

    float oacc[16][4];
    #pragma unroll
    for (int i = 0; i < 16; ++i)
        #pragma unroll
        for (int j = 0; j < 4; ++j) oacc[i][j] = 0.f;
    float mA = -1e30f, mB = -1e30f, lA = 0.f, lB = 0.f;

    // producer: 32-key fp32 K/V tile -> split -> bf16 planes (stage t&1)
    auto produce = [&](int t) {
        int e0 = (t & 1) * 4352;
        #pragma unroll 4
        for (int i = 0; i < 8; ++i) {
            int id = ptid + 128 * i;
            int row = id >> 5, c4 = (id & 31) << 2;
            int key = kb0 + t * 32 + row;
            const float *ks, *vs;
            if (key < STARTP) {
                size_t base = ((size_t)(b * 4096 + key) * 8 + kvh) * 128 + c4;
                ks = cache_k + base; vs = cache_v + base;
            } else {
                size_t rb = (size_t)(b * 16 + key - STARTP) * 6144 + kvh * 128 + c4;
                ks = qkv + rb + 4096; vs = qkv + rb + 5120;
            }
            float4 kvv = *(const float4*)ks;
            float4 vvv = *(const float4*)vs;
            uint32_t h0, l0, h1, l1;
            int e = e0 + row * 136 + c4;
            split2(kvv.x, kvv.y, h0, l0); split2(kvv.z, kvv.w, h1, l1);
            *(uint32_t*)&KV[e]        = h0; *(uint32_t*)&KV[e + 2]        = h1;
            *(uint32_t*)&KV[8704 + e] = l0; *(uint32_t*)&KV[8704 + e + 2] = l1;
            split2(vvv.x, vvv.y, h0, l0); split2(vvv.z, vvv.w, h1, l1);
            *(uint32_t*)&KV[17408 + e] = h0; *(uint32_t*)&KV[17408 + e + 2] = h1;
            *(uint32_t*)&KV[26112 + e] = l0; *(uint32_t*)&KV[26112 + e + 2] = l1;
        }
    };

    __syncthreads();              // Q planes visible
    if (w >= 4) produce(0);
    __syncthreads();

    for (int t = 0; t < 64; ++t) {
        const int s = t & 1;
        const uint32_t st_b = (uint32_t)(s * 4352 * 2);   // stage byte offset

        if (w >= 4) {
            if (t + 1 < 64) produce(t + 1);
        } else {
            // ---- S = Q K^T (16 rows x 32 keys) ----
            float sacc[4][4];
            #pragma unroll
            for (int nf = 0; nf < 4; ++nf)
                #pragma unroll
                for (int j = 0; j < 4; ++j) sacc[nf][j] = 0.f;

            #pragma unroll
            for (int kk = 0; kk < 8; ++kk) {
                int qrow = w*16 + (mt & 1)*8 + lr;
                int qcol = kk*16 + (mt >> 1)*8;
                uint32_t qfh[4], qfl[4];
                ldsm4(qfh, qh_b + (uint32_t)((qrow*136 + qcol)*2));
                ldsm4(qfl, ql_b + (uint32_t)((qrow*136 + qcol)*2));
                #pragma unroll
                for (int nfp = 0; nfp < 2; ++nfp) {
                    int krow = (nfp*2 + (mt >> 1))*8 + lr;
                    int kcol = kk*16 + (mt & 1)*8;
                    uint32_t off = st_b + (uint32_t)((krow*136 + kcol)*2);
                    uint32_t bh[4], bl[4];
                    ldsm4(bh, kv_b + kh_o + off);
                    ldsm4(bl, kv_b + kl_o + off);
                    #pragma unroll
                    for (int h = 0; h < 2; ++h) {
                        int nf = nfp*2 + h;
                        mma16(sacc[nf], qfh, bh[2*h], bh[2*h+1]);
                        mma16(sacc[nf], qfh, bl[2*h], bl[2*h+1]);
                        mma16(sacc[nf], qfl, bh[2*h], bh[2*h+1]);
                    }
                }
            }

            if (split == 1 && t == 63) {   // causal mask (keys 4064..4095)
                #pragma unroll
                for (int nf = 0; nf < 4; ++nf) {
                    int key = 4064 + nf*8 + 2*tig;
                    if (key     > STARTP + g)     sacc[nf][0] = -1e30f;
                    if (key + 1 > STARTP + g)     sacc[nf][1] = -1e30f;
                    if (key     > STARTP + g + 8) sacc[nf][2] = -1e30f;
                    if (key + 1 > STARTP + g + 8) sacc[nf][3] = -1e30f;
                }
            }

            // ---- online softmax (rows g and g+8) ----
            float tmA = -1e30f, tmB = -1e30f;
            #pragma unroll
            for (int nf = 0; nf < 4; ++nf) {
                tmA = fmaxf(tmA, fmaxf(sacc[nf][0], sacc[nf][1]));
                tmB = fmaxf(tmB, fmaxf(sacc[nf][2], sacc[nf][3]));
            }
            tmA = fmaxf(tmA, __shfl_xor_sync(0xffffffffu, tmA, 1));
            tmA = fmaxf(tmA, __shfl_xor_sync(0xffffffffu, tmA, 2));
            tmB = fmaxf(tmB, __shfl_xor_sync(0xffffffffu, tmB, 1));
            tmB = fmaxf(tmB, __shfl_xor_sync(0xffffffffu, tmB, 2));

            float mnA = fmaxf(mA, tmA), mnB = fmaxf(mB, tmB);
            float cA = __expf(mA - mnA), cB = __expf(mB - mnB);
            float psA = 0.f, psB = 0.f;
            #pragma unroll
            for (int nf = 0; nf < 4; ++nf) {
                sacc[nf][0] = __expf(sacc[nf][0] - mnA);
                sacc[nf][1] = __expf(sacc[nf][1] - mnA);
                sacc[nf][2] = __expf(sacc[nf][2] - mnB);
                sacc[nf][3] = __expf(sacc[nf][3] - mnB);
                psA += sacc[nf][0] + sacc[nf][1];
                psB += sacc[nf][2] + sacc[nf][3];
            }
            psA += __shfl_xor_sync(0xffffffffu, psA, 1);
            psA += __shfl_xor_sync(0xffffffffu, psA, 2);
            psB += __shfl_xor_sync(0xffffffffu, psB, 1);
            psB += __shfl_xor_sync(0xffffffffu, psB, 2);
            lA = lA * cA + psA; lB = lB * cB + psB;
            mA = mnA; mB = mnB;
            #pragma unroll
            for (int i = 0; i < 16; ++i) {
                oacc[i][0] *= cA; oacc[i][1] *= cA;
                oacc[i][2] *= cB; oacc[i][3] *= cB;
            }

            // ---- O += P V over the 32 keys ----
            #pragma unroll
            for (int kf = 0; kf < 2; ++kf) {
                uint32_t pah[4], pal[4];
                split2(sacc[2*kf][0],   sacc[2*kf][1],   pah[0], pal[0]);
                split2(sacc[2*kf][2],   sacc[2*kf][3],   pah[1], pal[1]);
                split2(sacc[2*kf+1][0], sacc[2*kf+1][1], pah[2], pal[2]);
                split2(sacc[2*kf+1][2], sacc[2*kf+1][3], pah[3], pal[3]);
                #pragma unroll
                for (int np = 0; np < 8; ++np) {
                    int vrow = kf*16 + (mt & 1)*8 + lr;
                    int vcol = (np*2 + (mt >> 1))*8;
                    uint32_t off = st_b + (uint32_t)((vrow*136 + vcol)*2);
                    uint32_t vh[4], vl[4];
                    ldsm4t(vh, kv_b + vh_o + off);
                    ldsm4t(vl, kv_b + vl_o + off);
                    #pragma unroll
                    for (int h = 0; h < 2; ++h) {
                        int nf2 = np*2 + h;
                        mma16(oacc[nf2], pah, vh[2*h], vh[2*h+1]);
                        mma16(oacc[nf2], pah, vl[2*h], vl[2*h+1]);
                        mma16(oacc[nf2], pal, vh[2*h], vh[2*h+1]);
                    }
                }
            }
        }
        __syncthreads();
    }

    // ---- write unnormalized partial O + (m, l) ----
    if (w < 4) {
        size_t poS = (size_t)split * (256 * 4096);
        size_t baseA = poS + (size_t)(b*16 + g    ) * 4096 + (kvh*4 + w) * 128;
        size_t baseB = poS + (size_t)(b*16 + g + 8) * 4096 + (kvh*4 + w) * 128;
        #pragma unroll
        for (int nf2 = 0; nf2 < 16; ++nf2) {
            int col = nf2*8 + 2*tig;
            *(float2*)&g_po[baseA + col] = make_float2(oacc[nf2][0], oacc[nf2][1]);
            *(float2*)&g_po[baseB + col] = make_float2(oacc[nf2][2], oacc[nf2][3]);
        }
        if (tig == 0) {
            int mlA = (split*8192 + (b*16 + g    )*32 + kvh*4 + w) * 2;
            int mlB = (split*8192 + (b*16 + g + 8)*32 + kvh*4 + w) * 2;
            g_ml[mlA] = mA; g_ml[mlA + 1] = lA;
            g_ml[mlB] = mB; g_ml[mlB + 1] = lB;
        }
    }
}

// ---------------------------------------------------------------------------
// merge the two KV splits (exact log-sum-exp combine) -> bf16 hi/lo planes
// ---------------------------------------------------------------------------
__global__ __launch_bounds__(256) void merge_kernel()
{
    int gid = blockIdx.x * 256 + threadIdx.x;   // < 524288
    int row = gid >> 11;                        // 0..255
    int pr  = gid & 2047;
    int d0  = pr * 2;
    int hg  = d0 >> 7;
    int mi  = (row*32 + hg) * 2;
    float m0 = g_ml[mi],         l0 = g_ml[mi + 1];
    float m1 = g_ml[16384 + mi], l1 = g_ml[16384 + mi + 1];
    float ms = fmaxf(m0, m1);
    float e0 = __expf(m0 - ms), e1 = __expf(m1 - ms);
    float r = 1.f / (l0*e0 + l1*e1);
    size_t o = (size_t)row * 4096 + d0;
    float2 p0 = *(float2*)&g_po[o];
    float2 p1 = *(float2*)&g_po[1048576 + o];
    float a  = (p0.x*e0 + p1.x*e1) * r;
    float bb = (p0.y*e0 + p1.y*e1) * r;
    uint32_t h, l;
    split2(a, bb, h, l);
    *(uint32_t*)&g_at_h[o] = h;
    *(uint32_t*)&g_at_l[o] = l;
}

// ---------------------------------------------------------------------------
extern "C" void kernel_launch(void* const* d_in, const int* in_sizes, int n_in,
                              void* d_out, int out_size)
{
    const float* x  = (const float*)d_in[0];
    const float* fc = (const float*)d_in[1];
    const float* fs = (const float*)d_in[2];
    const float* ck = (const float*)d_in[4];
    const float* cv = (const float*)d_in[5];
    const float* wq = (const float*)d_in[6];
    const float* bq = (const float*)d_in[7];
    const float* wk = (const float*)d_in[8];
    const float* bk = (const float*)d_in[9];
    const float* wv = (const float*)d_in[10];
    const float* bv = (const float*)d_in[11];
    const float* wo = (const float*)d_in[12];
    const float* bo = (const float*)d_in[13];
    float* out = (float*)d_out;

    __nv_bfloat16 *x_h, *x_l, *at_h, *at_l;
    float* qkv;
    cudaGetSymbolAddress((void**)&x_h,  g_x_h);  cudaGetSymbolAddress((void**)&x_l,  g_x_l);
    cudaGetSymbolAddress((void**)&at_h, g_at_h); cudaGetSymbolAddress((void**)&at_l, g_at_l);
    cudaGetSymbolAddress((void**)&qkv,  g_qkv);

    const int gemm_smem = (2*2*64*40 + 2*2*32*72) * 2;    // 38912 B
    const int attn_smem = (2*8704 + 4*2*4352) * 2;        // 104448 B
    cudaFuncSetAttribute(gemm_bf16x3<true>,
                         cudaFuncAttributeMaxDynamicSharedMemorySize, gemm_smem);
    cudaFuncSetAttribute(gemm_bf16x3<false>,
                         cudaFuncAttributeMaxDynamicSharedMemorySize, gemm_smem);
    cudaFuncSetAttribute(attn_bf16x3,
                         cudaFuncAttributeMaxDynamicSharedMemorySize, attn_smem);

    // 1) split x -> bf16 planes
    convert_kernel<<<1024, 256>>>(x, x_h, x_l, 256*4096/4);

    // 2) fused QKV projection + RoPE (fp32 out into g_qkv); 384 blocks
    gemm_bf16x3<true><<<dim3(96, 4), 256, gemm_smem>>>(
        x_h, x_l,
        wq, 4096, bq, 4096,
        wk, 1024, bk, 5120,
        wv, 1024, bv,
        qkv, 6144, fc, fs);

    // 3) attention, split-KV x2: 256 blocks, 2 CTAs/SM
    attn_bf16x3<<<256, 256, attn_smem>>>(ck, cv);

    // 4) merge splits -> bf16 planes
    merge_kernel<<<2048, 256>>>();

    // 5) output projection -> d_out (fp32); 256 blocks
    gemm_bf16x3<false><<<dim3(64, 4), 256, gemm_smem>>>(
        at_h, at_l,
        wo, 4096, bo, 1 << 30,
        wo, 4096, bo, 1 << 30,
        wo, 4096, bo,
        out, 4096, nullptr, nullptr);
}